// round 15
// baseline (speedup 1.0000x reference)
#include <cuda_runtime.h>
#include <cuda_fp16.h>
#include <cstdint>

// ---------------------------------------------------------------------------
// GCN: fp16 feature gather with pairwise HADD2 (proven agg), fp32 accum,
// tf32 tensor-core GEMMs. Conv/MLP1 GEMMs use BN=128 (512-thread CTA) to
// halve redundant A reads; MLP2 keeps the proven BN=64 kernel.
// CSR build with 3-phase parallel scan (fused finalize).
// ---------------------------------------------------------------------------

#define N_MAX 100000
#define E_MAX 3200000
#define SCAN_CHUNK 4096
#define MAX_CHUNKS ((N_MAX + SCAN_CHUNK - 1) / SCAN_CHUNK + 1)

__device__ int    g_deg_in[N_MAX];
__device__ int    g_deg_out[N_MAX];
__device__ int    g_row_ptr[N_MAX + 1];
__device__ int    g_cursor[N_MAX];
__device__ int    g_partial[MAX_CHUNKS];
__device__ int    g_sorted_src[E_MAX];
__device__ float  g_out_norm[N_MAX];
__device__ float  g_in_norm[N_MAX];
__device__ __half g_xh[(size_t)N_MAX * 128];
__device__ __half g_h1h[(size_t)N_MAX * 128];
__device__ float  g_agg[(size_t)N_MAX * 128];
__device__ float  g_h[(size_t)N_MAX * 128];
__device__ float  g_h3[(size_t)N_MAX * 256];

// ---------------------------------------------------------------------------
__global__ void zero_deg_kernel(int n, int* deg_in, int* deg_out) {
    int i = blockIdx.x * blockDim.x + threadIdx.x;
    if (i < n) { deg_in[i] = 0; deg_out[i] = 0; }
}

__global__ void hist_kernel(int e, const int* __restrict__ src,
                            const int* __restrict__ dst,
                            int* deg_in, int* deg_out) {
    int i = blockIdx.x * blockDim.x + threadIdx.x;
    if (i < e) {
        atomicAdd(&deg_out[src[i]], 1);
        atomicAdd(&deg_in[dst[i]], 1);
    }
}

// --- 3-phase parallel scan over deg_in ---
__global__ void scan_p1_kernel(int n, const int* __restrict__ deg, int* __restrict__ partial) {
    __shared__ int wsum[32];
    int i0 = blockIdx.x * SCAN_CHUNK + threadIdx.x * 4;
    int t = 0;
    if (i0 + 3 < n) {
        int4 v = *reinterpret_cast<const int4*>(deg + i0);
        t = v.x + v.y + v.z + v.w;
    } else {
        #pragma unroll
        for (int k = 0; k < 4; k++) if (i0 + k < n) t += deg[i0 + k];
    }
    #pragma unroll
    for (int o = 16; o > 0; o >>= 1) t += __shfl_down_sync(0xffffffffu, t, o);
    if ((threadIdx.x & 31) == 0) wsum[threadIdx.x >> 5] = t;
    __syncthreads();
    if (threadIdx.x < 32) {
        int v = wsum[threadIdx.x];
        #pragma unroll
        for (int o = 16; o > 0; o >>= 1) v += __shfl_down_sync(0xffffffffu, v, o);
        if (threadIdx.x == 0) partial[blockIdx.x] = v;
    }
}

__global__ void scan_p2_kernel(int nb, int n, int* __restrict__ partial,
                               int* __restrict__ row_ptr) {
    __shared__ int wsum[32];
    int tid = threadIdx.x;
    int lane = tid & 31;
    int wid = tid >> 5;
    int v = (tid < nb) ? partial[tid] : 0;
    int x = v;
    #pragma unroll
    for (int o = 1; o < 32; o <<= 1) {
        int u = __shfl_up_sync(0xffffffffu, x, o);
        if (lane >= o) x += u;
    }
    if (lane == 31) wsum[wid] = x;
    __syncthreads();
    if (wid == 0) {
        int y = wsum[lane];
        #pragma unroll
        for (int o = 1; o < 32; o <<= 1) {
            int u = __shfl_up_sync(0xffffffffu, y, o);
            if (lane >= o) y += u;
        }
        wsum[lane] = y;
    }
    __syncthreads();
    int excl = x - v + (wid > 0 ? wsum[wid - 1] : 0);
    if (tid < nb) partial[tid] = excl;
    if (tid == nb - 1) row_ptr[n] = excl + v;
}

__global__ void scan_p3_kernel(int n, const int* __restrict__ deg_in,
                               const int* __restrict__ deg_out,
                               const int* __restrict__ partial,
                               int* __restrict__ row_ptr, int* __restrict__ cursor,
                               float* __restrict__ onorm, float* __restrict__ inorm) {
    __shared__ int wsum[32];
    int i0 = blockIdx.x * SCAN_CHUNK + threadIdx.x * 4;
    int v0 = 0, v1 = 0, v2 = 0, v3 = 0;
    int d0 = 1, d1 = 1, d2 = 1, d3 = 1;
    if (i0 + 3 < n) {
        int4 v = *reinterpret_cast<const int4*>(deg_in + i0);
        v0 = v.x; v1 = v.y; v2 = v.z; v3 = v.w;
        int4 d = *reinterpret_cast<const int4*>(deg_out + i0);
        d0 = d.x; d1 = d.y; d2 = d.z; d3 = d.w;
    } else {
        if (i0 + 0 < n) { v0 = deg_in[i0 + 0]; d0 = deg_out[i0 + 0]; }
        if (i0 + 1 < n) { v1 = deg_in[i0 + 1]; d1 = deg_out[i0 + 1]; }
        if (i0 + 2 < n) { v2 = deg_in[i0 + 2]; d2 = deg_out[i0 + 2]; }
        if (i0 + 3 < n) { v3 = deg_in[i0 + 3]; d3 = deg_out[i0 + 3]; }
    }
    int t = v0 + v1 + v2 + v3;
    int lane = threadIdx.x & 31;
    int wid = threadIdx.x >> 5;
    int x = t;
    #pragma unroll
    for (int o = 1; o < 32; o <<= 1) {
        int u = __shfl_up_sync(0xffffffffu, x, o);
        if (lane >= o) x += u;
    }
    if (lane == 31) wsum[wid] = x;
    __syncthreads();
    if (wid == 0) {
        int y = wsum[lane];
        #pragma unroll
        for (int o = 1; o < 32; o <<= 1) {
            int u = __shfl_up_sync(0xffffffffu, y, o);
            if (lane >= o) y += u;
        }
        wsum[lane] = y;
    }
    __syncthreads();
    int excl = partial[blockIdx.x] + (wid > 0 ? wsum[wid - 1] : 0) + (x - t);
    int e0 = excl, e1 = e0 + v0, e2 = e1 + v1, e3 = e2 + v2;
    if (i0 + 0 < n) {
        row_ptr[i0 + 0] = e0; cursor[i0 + 0] = e0;
        inorm[i0 + 0] = rsqrtf((float)max(v0, 1));
        onorm[i0 + 0] = rsqrtf((float)max(d0, 1));
    }
    if (i0 + 1 < n) {
        row_ptr[i0 + 1] = e1; cursor[i0 + 1] = e1;
        inorm[i0 + 1] = rsqrtf((float)max(v1, 1));
        onorm[i0 + 1] = rsqrtf((float)max(d1, 1));
    }
    if (i0 + 2 < n) {
        row_ptr[i0 + 2] = e2; cursor[i0 + 2] = e2;
        inorm[i0 + 2] = rsqrtf((float)max(v2, 1));
        onorm[i0 + 2] = rsqrtf((float)max(d2, 1));
    }
    if (i0 + 3 < n) {
        row_ptr[i0 + 3] = e3; cursor[i0 + 3] = e3;
        inorm[i0 + 3] = rsqrtf((float)max(v3, 1));
        onorm[i0 + 3] = rsqrtf((float)max(d3, 1));
    }
}

__global__ void scatter_kernel(int e, const int* __restrict__ src,
                               const int* __restrict__ dst,
                               int* cursor, int* __restrict__ sorted_src) {
    int i = blockIdx.x * blockDim.x + threadIdx.x;
    if (i < e) {
        int d = dst[i];
        int pos = atomicAdd(&cursor[d], 1);
        sorted_src[pos] = src[i];
    }
}

// xh[i, :] = fp16(x[i, :] * out_norm[i]); one thread per 4 features.
__global__ void convert_x_kernel(int n, const float* __restrict__ x,
                                 const float* __restrict__ onorm,
                                 __half* __restrict__ xh) {
    int idx = blockIdx.x * blockDim.x + threadIdx.x;
    if (idx >= n * 32) return;
    int row = idx >> 5;
    float s = onorm[row];
    float4 v = *reinterpret_cast<const float4*>(x + (size_t)idx * 4);
    __half2 o0 = __floats2half2_rn(v.x * s, v.y * s);
    __half2 o1 = __floats2half2_rn(v.z * s, v.w * s);
    uint2 ov;
    ov.x = *reinterpret_cast<uint32_t*>(&o0);
    ov.y = *reinterpret_cast<uint32_t*>(&o1);
    *reinterpret_cast<uint2*>(xh + (size_t)idx * 4) = ov;
}

// ---------------------------------------------------------------------------
__device__ __forceinline__ __half2 u2h(uint32_t u) {
    __half2 h;
    *reinterpret_cast<uint32_t*>(&h) = u;
    return h;
}

// fp16 gather aggregation with pairwise HADD2 (proven kernel).
__global__ void agg_hpair_kernel(int n, const __half* __restrict__ feat,
                                 const int* __restrict__ row_ptr,
                                 const int* __restrict__ srcs,
                                 const float* __restrict__ inorm,
                                 float* __restrict__ out) {
    int warp = (blockIdx.x * blockDim.x + threadIdx.x) >> 5;
    if (warp >= n) return;
    const int lane = threadIdx.x & 31;
    const int beg = row_ptr[warp];
    const int end = row_ptr[warp + 1];
    const __half* fl = feat + lane * 4;

    float a0 = 0.f, a1 = 0.f, a2 = 0.f, a3 = 0.f;
    float b0 = 0.f, b1 = 0.f, b2 = 0.f, b3 = 0.f;

    int i = beg;
    for (; i + 32 <= end; i += 32) {
        int s = __ldg(srcs + i + lane);
        #pragma unroll
        for (int j = 0; j < 32; j += 4) {
            int s0 = __shfl_sync(0xffffffffu, s, j + 0);
            int s1 = __shfl_sync(0xffffffffu, s, j + 1);
            int s2 = __shfl_sync(0xffffffffu, s, j + 2);
            int s3 = __shfl_sync(0xffffffffu, s, j + 3);
            uint2 w0 = *reinterpret_cast<const uint2*>(fl + (size_t)s0 * 128);
            uint2 w1 = *reinterpret_cast<const uint2*>(fl + (size_t)s1 * 128);
            uint2 w2 = *reinterpret_cast<const uint2*>(fl + (size_t)s2 * 128);
            uint2 w3 = *reinterpret_cast<const uint2*>(fl + (size_t)s3 * 128);
            __half2 p0 = __hadd2(u2h(w0.x), u2h(w1.x));
            __half2 p1 = __hadd2(u2h(w0.y), u2h(w1.y));
            __half2 q0 = __hadd2(u2h(w2.x), u2h(w3.x));
            __half2 q1 = __hadd2(u2h(w2.y), u2h(w3.y));
            float2 f;
            f = __half22float2(p0); a0 += f.x; a1 += f.y;
            f = __half22float2(p1); a2 += f.x; a3 += f.y;
            f = __half22float2(q0); b0 += f.x; b1 += f.y;
            f = __half22float2(q1); b2 += f.x; b3 += f.y;
        }
    }
    if (i < end) {
        int cnt = end - i;
        int s = 0;
        if (lane < cnt) s = __ldg(srcs + i + lane);
        int j = 0;
        for (; j + 2 <= cnt; j += 2) {
            int s0 = __shfl_sync(0xffffffffu, s, j + 0);
            int s1 = __shfl_sync(0xffffffffu, s, j + 1);
            uint2 w0 = *reinterpret_cast<const uint2*>(fl + (size_t)s0 * 128);
            uint2 w1 = *reinterpret_cast<const uint2*>(fl + (size_t)s1 * 128);
            __half2 p0 = __hadd2(u2h(w0.x), u2h(w1.x));
            __half2 p1 = __hadd2(u2h(w0.y), u2h(w1.y));
            float2 f;
            f = __half22float2(p0); a0 += f.x; a1 += f.y;
            f = __half22float2(p1); a2 += f.x; a3 += f.y;
        }
        if (j < cnt) {
            int s0 = __shfl_sync(0xffffffffu, s, j);
            uint2 w0 = *reinterpret_cast<const uint2*>(fl + (size_t)s0 * 128);
            float2 f;
            f = __half22float2(u2h(w0.x)); a0 += f.x; a1 += f.y;
            f = __half22float2(u2h(w0.y)); a2 += f.x; a3 += f.y;
        }
    }
    float iw = inorm[warp];
    float4 o = make_float4((a0 + b0) * iw, (a1 + b1) * iw,
                           (a2 + b2) * iw, (a3 + b3) * iw);
    *reinterpret_cast<float4*>(out + (size_t)warp * 128 + lane * 4) = o;
}

// ---------------------------------------------------------------------------
__device__ __forceinline__ uint32_t f2tf32(float x) {
    uint32_t r;
    asm("cvt.rna.tf32.f32 %0, %1;" : "=r"(r) : "f"(x));
    return r;
}

__device__ __forceinline__ void mma_tf32(float c[4], uint32_t a0, uint32_t a1,
                                         uint32_t a2, uint32_t a3,
                                         uint32_t b0, uint32_t b1) {
    asm volatile(
        "mma.sync.aligned.m16n8k8.row.col.f32.tf32.tf32.f32 "
        "{%0,%1,%2,%3}, {%4,%5,%6,%7}, {%8,%9}, {%0,%1,%2,%3};\n"
        : "+f"(c[0]), "+f"(c[1]), "+f"(c[2]), "+f"(c[3])
        : "r"(a0), "r"(a1), "r"(a2), "r"(a3), "r"(b0), "r"(b1));
}

// ---------------------------------------------------------------------------
// WIDE tf32 GEMM: block 128x128x32, 512 threads = 16 warps (4M x 4N),
// warp tile 32x32. Halves redundant A reads vs BN=64.
// ---------------------------------------------------------------------------
template <bool RELU, bool PSCALE, bool OUTH>
__global__ __launch_bounds__(512) void gemm_tf32_wide_kernel(
        int M, int K, int ldn,
        const float* __restrict__ A,
        const float* __restrict__ W,
        const float* __restrict__ bias,
        const float* __restrict__ pscale,
        void* __restrict__ Cout) {
    constexpr int BM = 128, BN = 128, BK = 32;
    constexpr int ASTR = BK + 4;   // 36 words
    constexpr int WSTR = BN + 4;   // 132 words
    __shared__ uint32_t As[BM * ASTR];
    __shared__ uint32_t Ws[BK * WSTR];

    const int tid = threadIdx.x;
    const int lane = tid & 31;
    const int wid = tid >> 5;
    const int g = lane >> 2;
    const int tig = lane & 3;
    const int warpM = (wid & 3) * 32;
    const int warpN = (wid >> 2) * 32;
    const int rowBase = blockIdx.x * BM;
    const int nBase = blockIdx.y * BN;

    float4 ra[2];
    float4 rw[2];

    auto loadA = [&](int kb) {
        #pragma unroll
        for (int i = 0; i < 2; i++) {
            int id = tid + i * 512;        // 0..1023
            int row = id >> 3;             // 0..127
            int c4 = (id & 7) * 4;         // 0..28
            int grow = rowBase + row;
            if (grow < M)
                ra[i] = *reinterpret_cast<const float4*>(A + (size_t)grow * K + kb + c4);
            else
                ra[i] = make_float4(0.f, 0.f, 0.f, 0.f);
        }
    };
    auto loadW = [&](int kb) {
        #pragma unroll
        for (int i = 0; i < 2; i++) {
            int id = tid + i * 512;        // 0..1023
            int row = id >> 5;             // 0..31
            int c4 = (id & 31) * 4;        // 0..124
            rw[i] = *reinterpret_cast<const float4*>(W + (size_t)(kb + row) * ldn + nBase + c4);
        }
    };
    auto storeA = [&]() {
        #pragma unroll
        for (int i = 0; i < 2; i++) {
            int id = tid + i * 512;
            int row = id >> 3;
            int c4 = (id & 7) * 4;
            uint32_t* p = &As[row * ASTR + c4];
            p[0] = f2tf32(ra[i].x);
            p[1] = f2tf32(ra[i].y);
            p[2] = f2tf32(ra[i].z);
            p[3] = f2tf32(ra[i].w);
        }
    };
    auto storeW = [&]() {
        #pragma unroll
        for (int i = 0; i < 2; i++) {
            int id = tid + i * 512;
            int row = id >> 5;
            int c4 = (id & 31) * 4;
            uint32_t* p = &Ws[row * WSTR + c4];
            p[0] = f2tf32(rw[i].x);
            p[1] = f2tf32(rw[i].y);
            p[2] = f2tf32(rw[i].z);
            p[3] = f2tf32(rw[i].w);
        }
    };

    float acc[2][4][4];
    #pragma unroll
    for (int m = 0; m < 2; m++)
        #pragma unroll
        for (int n = 0; n < 4; n++)
            #pragma unroll
            for (int q = 0; q < 4; q++) acc[m][n][q] = 0.f;

    loadA(0);
    loadW(0);

    for (int kb = 0; kb < K; kb += BK) {
        storeA();
        storeW();
        __syncthreads();
        if (kb + BK < K) { loadA(kb + BK); loadW(kb + BK); }

        #pragma unroll
        for (int ks = 0; ks < BK; ks += 8) {
            uint32_t af[2][4];
            #pragma unroll
            for (int m = 0; m < 2; m++) {
                int r0 = warpM + m * 16 + g;
                int r1 = r0 + 8;
                af[m][0] = As[r0 * ASTR + ks + tig];
                af[m][1] = As[r1 * ASTR + ks + tig];
                af[m][2] = As[r0 * ASTR + ks + tig + 4];
                af[m][3] = As[r1 * ASTR + ks + tig + 4];
            }
            uint32_t bf[4][2];
            #pragma unroll
            for (int n = 0; n < 4; n++) {
                int cn = warpN + n * 8 + g;
                bf[n][0] = Ws[(ks + tig) * WSTR + cn];
                bf[n][1] = Ws[(ks + tig + 4) * WSTR + cn];
            }
            #pragma unroll
            for (int m = 0; m < 2; m++)
                #pragma unroll
                for (int n = 0; n < 4; n++)
                    mma_tf32(acc[m][n], af[m][0], af[m][1], af[m][2], af[m][3],
                             bf[n][0], bf[n][1]);
        }
        __syncthreads();
    }

    #pragma unroll
    for (int n = 0; n < 4; n++) {
        int col = nBase + warpN + n * 8 + tig * 2;
        float bv0 = bias[col];
        float bv1 = bias[col + 1];
        #pragma unroll
        for (int m = 0; m < 2; m++) {
            #pragma unroll
            for (int hf = 0; hf < 2; hf++) {
                int row = rowBase + warpM + m * 16 + g + hf * 8;
                if (row >= M) continue;
                float sc = PSCALE ? pscale[row] : 1.f;
                float o0 = acc[m][n][hf * 2 + 0] + bv0;
                float o1 = acc[m][n][hf * 2 + 1] + bv1;
                if (RELU) { o0 = fmaxf(o0, 0.f); o1 = fmaxf(o1, 0.f); }
                o0 *= sc; o1 *= sc;
                if (OUTH) {
                    __half2 o = __floats2half2_rn(o0, o1);
                    *reinterpret_cast<__half2*>((__half*)Cout + (size_t)row * ldn + col) = o;
                } else {
                    *reinterpret_cast<float2*>((float*)Cout + (size_t)row * ldn + col) =
                        make_float2(o0, o1);
                }
            }
        }
    }
}

// ---------------------------------------------------------------------------
// Narrow tf32 GEMM (proven BN=64 kernel) — used for MLP2 (N=64).
// ---------------------------------------------------------------------------
template <bool RELU, bool PSCALE, bool OUTH>
__global__ __launch_bounds__(256) void gemm_tf32_kernel(
        int M, int K, int ldn,
        const float* __restrict__ A,
        const float* __restrict__ W,
        const float* __restrict__ bias,
        const float* __restrict__ pscale,
        void* __restrict__ Cout) {
    constexpr int BM = 128, BN = 64, BK = 32;
    constexpr int ASTR = BK + 4;
    constexpr int WSTR = BN + 4;
    __shared__ uint32_t As[BM * ASTR];
    __shared__ uint32_t Ws[BK * WSTR];

    const int tid = threadIdx.x;
    const int lane = tid & 31;
    const int wid = tid >> 5;
    const int g = lane >> 2;
    const int tig = lane & 3;
    const int warpM = (wid & 3) * 32;
    const int warpN = (wid >> 2) * 32;
    const int rowBase = blockIdx.x * BM;
    const int nBase = blockIdx.y * BN;

    float4 ra[4];
    float4 rw[2];

    auto loadA = [&](int kb) {
        #pragma unroll
        for (int i = 0; i < 4; i++) {
            int id = tid + i * 256;
            int row = id >> 3;
            int c4 = (id & 7) * 4;
            int grow = rowBase + row;
            if (grow < M)
                ra[i] = *reinterpret_cast<const float4*>(A + (size_t)grow * K + kb + c4);
            else
                ra[i] = make_float4(0.f, 0.f, 0.f, 0.f);
        }
    };
    auto loadW = [&](int kb) {
        #pragma unroll
        for (int i = 0; i < 2; i++) {
            int id = tid + i * 256;
            int row = id >> 4;
            int c4 = (id & 15) * 4;
            rw[i] = *reinterpret_cast<const float4*>(W + (size_t)(kb + row) * ldn + nBase + c4);
        }
    };
    auto storeA = [&]() {
        #pragma unroll
        for (int i = 0; i < 4; i++) {
            int id = tid + i * 256;
            int row = id >> 3;
            int c4 = (id & 7) * 4;
            uint32_t* p = &As[row * ASTR + c4];
            p[0] = f2tf32(ra[i].x);
            p[1] = f2tf32(ra[i].y);
            p[2] = f2tf32(ra[i].z);
            p[3] = f2tf32(ra[i].w);
        }
    };
    auto storeW = [&]() {
        #pragma unroll
        for (int i = 0; i < 2; i++) {
            int id = tid + i * 256;
            int row = id >> 4;
            int c4 = (id & 15) * 4;
            uint32_t* p = &Ws[row * WSTR + c4];
            p[0] = f2tf32(rw[i].x);
            p[1] = f2tf32(rw[i].y);
            p[2] = f2tf32(rw[i].z);
            p[3] = f2tf32(rw[i].w);
        }
    };

    float acc[2][4][4];
    #pragma unroll
    for (int m = 0; m < 2; m++)
        #pragma unroll
        for (int n = 0; n < 4; n++)
            #pragma unroll
            for (int q = 0; q < 4; q++) acc[m][n][q] = 0.f;

    loadA(0);
    loadW(0);

    for (int kb = 0; kb < K; kb += BK) {
        storeA();
        storeW();
        __syncthreads();
        if (kb + BK < K) { loadA(kb + BK); loadW(kb + BK); }

        #pragma unroll
        for (int ks = 0; ks < BK; ks += 8) {
            uint32_t af[2][4];
            #pragma unroll
            for (int m = 0; m < 2; m++) {
                int r0 = warpM + m * 16 + g;
                int r1 = r0 + 8;
                af[m][0] = As[r0 * ASTR + ks + tig];
                af[m][1] = As[r1 * ASTR + ks + tig];
                af[m][2] = As[r0 * ASTR + ks + tig + 4];
                af[m][3] = As[r1 * ASTR + ks + tig + 4];
            }
            uint32_t bf[4][2];
            #pragma unroll
            for (int n = 0; n < 4; n++) {
                int cn = warpN + n * 8 + g;
                bf[n][0] = Ws[(ks + tig) * WSTR + cn];
                bf[n][1] = Ws[(ks + tig + 4) * WSTR + cn];
            }
            #pragma unroll
            for (int m = 0; m < 2; m++)
                #pragma unroll
                for (int n = 0; n < 4; n++)
                    mma_tf32(acc[m][n], af[m][0], af[m][1], af[m][2], af[m][3],
                             bf[n][0], bf[n][1]);
        }
        __syncthreads();
    }

    #pragma unroll
    for (int n = 0; n < 4; n++) {
        int col = nBase + warpN + n * 8 + tig * 2;
        float bv0 = bias[col];
        float bv1 = bias[col + 1];
        #pragma unroll
        for (int m = 0; m < 2; m++) {
            #pragma unroll
            for (int hf = 0; hf < 2; hf++) {
                int row = rowBase + warpM + m * 16 + g + hf * 8;
                if (row >= M) continue;
                float sc = PSCALE ? pscale[row] : 1.f;
                float o0 = acc[m][n][hf * 2 + 0] + bv0;
                float o1 = acc[m][n][hf * 2 + 1] + bv1;
                if (RELU) { o0 = fmaxf(o0, 0.f); o1 = fmaxf(o1, 0.f); }
                o0 *= sc; o1 *= sc;
                if (OUTH) {
                    __half2 o = __floats2half2_rn(o0, o1);
                    *reinterpret_cast<__half2*>((__half*)Cout + (size_t)row * ldn + col) = o;
                } else {
                    *reinterpret_cast<float2*>((float*)Cout + (size_t)row * ldn + col) =
                        make_float2(o0, o1);
                }
            }
        }
    }
}

// ---------------------------------------------------------------------------
extern "C" void kernel_launch(void* const* d_in, const int* in_sizes, int n_in,
                              void* d_out, int out_size) {
    const float* x   = (const float*)d_in[0];
    const int*   src = (const int*)d_in[1];
    const int*   dst = (const int*)d_in[2];
    const float* w1  = (const float*)d_in[3];
    const float* b1  = (const float*)d_in[4];
    const float* w2  = (const float*)d_in[5];
    const float* b2  = (const float*)d_in[6];
    const float* wm1 = (const float*)d_in[7];
    const float* bm1 = (const float*)d_in[8];
    const float* wm2 = (const float*)d_in[9];
    const float* bm2 = (const float*)d_in[10];

    const int n = in_sizes[0] / 128;
    const int e = in_sizes[1];

    int *deg_in, *deg_out, *row_ptr, *cursor, *sorted_src, *partial;
    float *onorm, *inorm, *agg, *h, *h3;
    __half *xh, *h1h;
    cudaGetSymbolAddress((void**)&deg_in, g_deg_in);
    cudaGetSymbolAddress((void**)&deg_out, g_deg_out);
    cudaGetSymbolAddress((void**)&row_ptr, g_row_ptr);
    cudaGetSymbolAddress((void**)&cursor, g_cursor);
    cudaGetSymbolAddress((void**)&partial, g_partial);
    cudaGetSymbolAddress((void**)&sorted_src, g_sorted_src);
    cudaGetSymbolAddress((void**)&onorm, g_out_norm);
    cudaGetSymbolAddress((void**)&inorm, g_in_norm);
    cudaGetSymbolAddress((void**)&xh, g_xh);
    cudaGetSymbolAddress((void**)&h1h, g_h1h);
    cudaGetSymbolAddress((void**)&agg, g_agg);
    cudaGetSymbolAddress((void**)&h, g_h);
    cudaGetSymbolAddress((void**)&h3, g_h3);

    const int nb = (n + 255) / 256;
    const int eb = (e + 511) / 512;
    const int nChunks = (n + SCAN_CHUNK - 1) / SCAN_CHUNK;

    // --- CSR build (parallel 3-phase scan, finalize fused into phase 3) ---
    zero_deg_kernel<<<nb, 256>>>(n, deg_in, deg_out);
    hist_kernel<<<eb, 512>>>(e, src, dst, deg_in, deg_out);
    scan_p1_kernel<<<nChunks, 1024>>>(n, deg_in, partial);
    scan_p2_kernel<<<1, 1024>>>(nChunks, n, partial, row_ptr);
    scan_p3_kernel<<<nChunks, 1024>>>(n, deg_in, deg_out, partial,
                                      row_ptr, cursor, onorm, inorm);
    scatter_kernel<<<eb, 512>>>(e, src, dst, cursor, sorted_src);

    // --- x -> fp16 prescaled by out_norm ---
    convert_x_kernel<<<(n * 32 + 255) / 256, 256>>>(n, x, onorm, xh);

    const int aggBlocks = (n + 7) / 8;
    const dim3 gw1((n + 127) / 128, 1);   // wide, N=128
    const dim3 gw2((n + 127) / 128, 2);   // wide, N=256
    const dim3 g1((n + 127) / 128, 1);    // narrow, N=64

    // --- conv1 ---
    agg_hpair_kernel<<<aggBlocks, 256>>>(n, xh, row_ptr, sorted_src, inorm, agg);
    gemm_tf32_wide_kernel<true, true, true><<<gw1, 512>>>(n, 128, 128, agg, w1, b1, onorm, h1h);

    // --- conv2 ---
    agg_hpair_kernel<<<aggBlocks, 256>>>(n, h1h, row_ptr, sorted_src, inorm, agg);
    gemm_tf32_wide_kernel<true, false, false><<<gw1, 512>>>(n, 128, 128, agg, w2, b2, nullptr, h);

    // --- MLP ---
    gemm_tf32_wide_kernel<true, false, false><<<gw2, 512>>>(n, 128, 256, h, wm1, bm1, nullptr, h3);
    gemm_tf32_kernel<false, false, false><<<g1, 256>>>(n, 256, 64, h3, wm2, bm2, nullptr, d_out);
}

// round 16
// speedup vs baseline: 1.0399x; 1.0399x over previous
#include <cuda_runtime.h>
#include <cuda_fp16.h>
#include <cstdint>

// ---------------------------------------------------------------------------
// GCN: fp16 feature gather with pairwise HADD2 (proven agg), fp32 accum,
// tf32 GEMMs (proven BN=64) for conv1/conv2/MLP1; MLP1 hidden stored fp16
// (mantissa-equivalent to tf32 rounding), MLP2 via proven f16-mma GEMM.
// CSR build with 3-phase parallel scan (fused finalize).
// ---------------------------------------------------------------------------

#define N_MAX 100000
#define E_MAX 3200000
#define SCAN_CHUNK 4096
#define MAX_CHUNKS ((N_MAX + SCAN_CHUNK - 1) / SCAN_CHUNK + 1)

__device__ int    g_deg_in[N_MAX];
__device__ int    g_deg_out[N_MAX];
__device__ int    g_row_ptr[N_MAX + 1];
__device__ int    g_cursor[N_MAX];
__device__ int    g_partial[MAX_CHUNKS];
__device__ int    g_sorted_src[E_MAX];
__device__ float  g_out_norm[N_MAX];
__device__ float  g_in_norm[N_MAX];
__device__ __half g_xh[(size_t)N_MAX * 128];
__device__ __half g_h1h[(size_t)N_MAX * 128];
__device__ float  g_agg[(size_t)N_MAX * 128];
__device__ float  g_h[(size_t)N_MAX * 128];
__device__ __half g_h3h[(size_t)N_MAX * 256];

// ---------------------------------------------------------------------------
__global__ void zero_deg_kernel(int n, int* deg_in, int* deg_out) {
    int i = blockIdx.x * blockDim.x + threadIdx.x;
    if (i < n) { deg_in[i] = 0; deg_out[i] = 0; }
}

__global__ void hist_kernel(int e, const int* __restrict__ src,
                            const int* __restrict__ dst,
                            int* deg_in, int* deg_out) {
    int i = blockIdx.x * blockDim.x + threadIdx.x;
    if (i < e) {
        atomicAdd(&deg_out[src[i]], 1);
        atomicAdd(&deg_in[dst[i]], 1);
    }
}

// --- 3-phase parallel scan over deg_in ---
__global__ void scan_p1_kernel(int n, const int* __restrict__ deg, int* __restrict__ partial) {
    __shared__ int wsum[32];
    int i0 = blockIdx.x * SCAN_CHUNK + threadIdx.x * 4;
    int t = 0;
    if (i0 + 3 < n) {
        int4 v = *reinterpret_cast<const int4*>(deg + i0);
        t = v.x + v.y + v.z + v.w;
    } else {
        #pragma unroll
        for (int k = 0; k < 4; k++) if (i0 + k < n) t += deg[i0 + k];
    }
    #pragma unroll
    for (int o = 16; o > 0; o >>= 1) t += __shfl_down_sync(0xffffffffu, t, o);
    if ((threadIdx.x & 31) == 0) wsum[threadIdx.x >> 5] = t;
    __syncthreads();
    if (threadIdx.x < 32) {
        int v = wsum[threadIdx.x];
        #pragma unroll
        for (int o = 16; o > 0; o >>= 1) v += __shfl_down_sync(0xffffffffu, v, o);
        if (threadIdx.x == 0) partial[blockIdx.x] = v;
    }
}

__global__ void scan_p2_kernel(int nb, int n, int* __restrict__ partial,
                               int* __restrict__ row_ptr) {
    __shared__ int wsum[32];
    int tid = threadIdx.x;
    int lane = tid & 31;
    int wid = tid >> 5;
    int v = (tid < nb) ? partial[tid] : 0;
    int x = v;
    #pragma unroll
    for (int o = 1; o < 32; o <<= 1) {
        int u = __shfl_up_sync(0xffffffffu, x, o);
        if (lane >= o) x += u;
    }
    if (lane == 31) wsum[wid] = x;
    __syncthreads();
    if (wid == 0) {
        int y = wsum[lane];
        #pragma unroll
        for (int o = 1; o < 32; o <<= 1) {
            int u = __shfl_up_sync(0xffffffffu, y, o);
            if (lane >= o) y += u;
        }
        wsum[lane] = y;
    }
    __syncthreads();
    int excl = x - v + (wid > 0 ? wsum[wid - 1] : 0);
    if (tid < nb) partial[tid] = excl;
    if (tid == nb - 1) row_ptr[n] = excl + v;
}

__global__ void scan_p3_kernel(int n, const int* __restrict__ deg_in,
                               const int* __restrict__ deg_out,
                               const int* __restrict__ partial,
                               int* __restrict__ row_ptr, int* __restrict__ cursor,
                               float* __restrict__ onorm, float* __restrict__ inorm) {
    __shared__ int wsum[32];
    int i0 = blockIdx.x * SCAN_CHUNK + threadIdx.x * 4;
    int v0 = 0, v1 = 0, v2 = 0, v3 = 0;
    int d0 = 1, d1 = 1, d2 = 1, d3 = 1;
    if (i0 + 3 < n) {
        int4 v = *reinterpret_cast<const int4*>(deg_in + i0);
        v0 = v.x; v1 = v.y; v2 = v.z; v3 = v.w;
        int4 d = *reinterpret_cast<const int4*>(deg_out + i0);
        d0 = d.x; d1 = d.y; d2 = d.z; d3 = d.w;
    } else {
        if (i0 + 0 < n) { v0 = deg_in[i0 + 0]; d0 = deg_out[i0 + 0]; }
        if (i0 + 1 < n) { v1 = deg_in[i0 + 1]; d1 = deg_out[i0 + 1]; }
        if (i0 + 2 < n) { v2 = deg_in[i0 + 2]; d2 = deg_out[i0 + 2]; }
        if (i0 + 3 < n) { v3 = deg_in[i0 + 3]; d3 = deg_out[i0 + 3]; }
    }
    int t = v0 + v1 + v2 + v3;
    int lane = threadIdx.x & 31;
    int wid = threadIdx.x >> 5;
    int x = t;
    #pragma unroll
    for (int o = 1; o < 32; o <<= 1) {
        int u = __shfl_up_sync(0xffffffffu, x, o);
        if (lane >= o) x += u;
    }
    if (lane == 31) wsum[wid] = x;
    __syncthreads();
    if (wid == 0) {
        int y = wsum[lane];
        #pragma unroll
        for (int o = 1; o < 32; o <<= 1) {
            int u = __shfl_up_sync(0xffffffffu, y, o);
            if (lane >= o) y += u;
        }
        wsum[lane] = y;
    }
    __syncthreads();
    int excl = partial[blockIdx.x] + (wid > 0 ? wsum[wid - 1] : 0) + (x - t);
    int e0 = excl, e1 = e0 + v0, e2 = e1 + v1, e3 = e2 + v2;
    if (i0 + 0 < n) {
        row_ptr[i0 + 0] = e0; cursor[i0 + 0] = e0;
        inorm[i0 + 0] = rsqrtf((float)max(v0, 1));
        onorm[i0 + 0] = rsqrtf((float)max(d0, 1));
    }
    if (i0 + 1 < n) {
        row_ptr[i0 + 1] = e1; cursor[i0 + 1] = e1;
        inorm[i0 + 1] = rsqrtf((float)max(v1, 1));
        onorm[i0 + 1] = rsqrtf((float)max(d1, 1));
    }
    if (i0 + 2 < n) {
        row_ptr[i0 + 2] = e2; cursor[i0 + 2] = e2;
        inorm[i0 + 2] = rsqrtf((float)max(v2, 1));
        onorm[i0 + 2] = rsqrtf((float)max(d2, 1));
    }
    if (i0 + 3 < n) {
        row_ptr[i0 + 3] = e3; cursor[i0 + 3] = e3;
        inorm[i0 + 3] = rsqrtf((float)max(v3, 1));
        onorm[i0 + 3] = rsqrtf((float)max(d3, 1));
    }
}

__global__ void scatter_kernel(int e, const int* __restrict__ src,
                               const int* __restrict__ dst,
                               int* cursor, int* __restrict__ sorted_src) {
    int i = blockIdx.x * blockDim.x + threadIdx.x;
    if (i < e) {
        int d = dst[i];
        int pos = atomicAdd(&cursor[d], 1);
        sorted_src[pos] = src[i];
    }
}

// xh[i, :] = fp16(x[i, :] * out_norm[i]); one thread per 4 features.
__global__ void convert_x_kernel(int n, const float* __restrict__ x,
                                 const float* __restrict__ onorm,
                                 __half* __restrict__ xh) {
    int idx = blockIdx.x * blockDim.x + threadIdx.x;
    if (idx >= n * 32) return;
    int row = idx >> 5;
    float s = onorm[row];
    float4 v = *reinterpret_cast<const float4*>(x + (size_t)idx * 4);
    __half2 o0 = __floats2half2_rn(v.x * s, v.y * s);
    __half2 o1 = __floats2half2_rn(v.z * s, v.w * s);
    uint2 ov;
    ov.x = *reinterpret_cast<uint32_t*>(&o0);
    ov.y = *reinterpret_cast<uint32_t*>(&o1);
    *reinterpret_cast<uint2*>(xh + (size_t)idx * 4) = ov;
}

// ---------------------------------------------------------------------------
__device__ __forceinline__ __half2 u2h(uint32_t u) {
    __half2 h;
    *reinterpret_cast<uint32_t*>(&h) = u;
    return h;
}

// fp16 gather aggregation with pairwise HADD2 (proven kernel).
__global__ void agg_hpair_kernel(int n, const __half* __restrict__ feat,
                                 const int* __restrict__ row_ptr,
                                 const int* __restrict__ srcs,
                                 const float* __restrict__ inorm,
                                 float* __restrict__ out) {
    int warp = (blockIdx.x * blockDim.x + threadIdx.x) >> 5;
    if (warp >= n) return;
    const int lane = threadIdx.x & 31;
    const int beg = row_ptr[warp];
    const int end = row_ptr[warp + 1];
    const __half* fl = feat + lane * 4;

    float a0 = 0.f, a1 = 0.f, a2 = 0.f, a3 = 0.f;
    float b0 = 0.f, b1 = 0.f, b2 = 0.f, b3 = 0.f;

    int i = beg;
    for (; i + 32 <= end; i += 32) {
        int s = __ldg(srcs + i + lane);
        #pragma unroll
        for (int j = 0; j < 32; j += 4) {
            int s0 = __shfl_sync(0xffffffffu, s, j + 0);
            int s1 = __shfl_sync(0xffffffffu, s, j + 1);
            int s2 = __shfl_sync(0xffffffffu, s, j + 2);
            int s3 = __shfl_sync(0xffffffffu, s, j + 3);
            uint2 w0 = *reinterpret_cast<const uint2*>(fl + (size_t)s0 * 128);
            uint2 w1 = *reinterpret_cast<const uint2*>(fl + (size_t)s1 * 128);
            uint2 w2 = *reinterpret_cast<const uint2*>(fl + (size_t)s2 * 128);
            uint2 w3 = *reinterpret_cast<const uint2*>(fl + (size_t)s3 * 128);
            __half2 p0 = __hadd2(u2h(w0.x), u2h(w1.x));
            __half2 p1 = __hadd2(u2h(w0.y), u2h(w1.y));
            __half2 q0 = __hadd2(u2h(w2.x), u2h(w3.x));
            __half2 q1 = __hadd2(u2h(w2.y), u2h(w3.y));
            float2 f;
            f = __half22float2(p0); a0 += f.x; a1 += f.y;
            f = __half22float2(p1); a2 += f.x; a3 += f.y;
            f = __half22float2(q0); b0 += f.x; b1 += f.y;
            f = __half22float2(q1); b2 += f.x; b3 += f.y;
        }
    }
    if (i < end) {
        int cnt = end - i;
        int s = 0;
        if (lane < cnt) s = __ldg(srcs + i + lane);
        int j = 0;
        for (; j + 2 <= cnt; j += 2) {
            int s0 = __shfl_sync(0xffffffffu, s, j + 0);
            int s1 = __shfl_sync(0xffffffffu, s, j + 1);
            uint2 w0 = *reinterpret_cast<const uint2*>(fl + (size_t)s0 * 128);
            uint2 w1 = *reinterpret_cast<const uint2*>(fl + (size_t)s1 * 128);
            __half2 p0 = __hadd2(u2h(w0.x), u2h(w1.x));
            __half2 p1 = __hadd2(u2h(w0.y), u2h(w1.y));
            float2 f;
            f = __half22float2(p0); a0 += f.x; a1 += f.y;
            f = __half22float2(p1); a2 += f.x; a3 += f.y;
        }
        if (j < cnt) {
            int s0 = __shfl_sync(0xffffffffu, s, j);
            uint2 w0 = *reinterpret_cast<const uint2*>(fl + (size_t)s0 * 128);
            float2 f;
            f = __half22float2(u2h(w0.x)); a0 += f.x; a1 += f.y;
            f = __half22float2(u2h(w0.y)); a2 += f.x; a3 += f.y;
        }
    }
    float iw = inorm[warp];
    float4 o = make_float4((a0 + b0) * iw, (a1 + b1) * iw,
                           (a2 + b2) * iw, (a3 + b3) * iw);
    *reinterpret_cast<float4*>(out + (size_t)warp * 128 + lane * 4) = o;
}

// ---------------------------------------------------------------------------
__device__ __forceinline__ uint32_t f2tf32(float x) {
    uint32_t r;
    asm("cvt.rna.tf32.f32 %0, %1;" : "=r"(r) : "f"(x));
    return r;
}

__device__ __forceinline__ void mma_tf32(float c[4], uint32_t a0, uint32_t a1,
                                         uint32_t a2, uint32_t a3,
                                         uint32_t b0, uint32_t b1) {
    asm volatile(
        "mma.sync.aligned.m16n8k8.row.col.f32.tf32.tf32.f32 "
        "{%0,%1,%2,%3}, {%4,%5,%6,%7}, {%8,%9}, {%0,%1,%2,%3};\n"
        : "+f"(c[0]), "+f"(c[1]), "+f"(c[2]), "+f"(c[3])
        : "r"(a0), "r"(a1), "r"(a2), "r"(a3), "r"(b0), "r"(b1));
}

__device__ __forceinline__ void mma_f16(float c[4], uint32_t a0, uint32_t a1,
                                        uint32_t a2, uint32_t a3,
                                        uint32_t b0, uint32_t b1) {
    asm volatile(
        "mma.sync.aligned.m16n8k16.row.col.f32.f16.f16.f32 "
        "{%0,%1,%2,%3}, {%4,%5,%6,%7}, {%8,%9}, {%0,%1,%2,%3};\n"
        : "+f"(c[0]), "+f"(c[1]), "+f"(c[2]), "+f"(c[3])
        : "r"(a0), "r"(a1), "r"(a2), "r"(a3), "r"(b0), "r"(b1));
}

// ---------------------------------------------------------------------------
// tf32 tensor-core GEMM (proven BN=64 kernel). Block 128x64x32, 8 warps.
// ---------------------------------------------------------------------------
template <bool RELU, bool PSCALE, bool OUTH>
__global__ __launch_bounds__(256) void gemm_tf32_kernel(
        int M, int K, int ldn,
        const float* __restrict__ A,
        const float* __restrict__ W,
        const float* __restrict__ bias,
        const float* __restrict__ pscale,
        void* __restrict__ Cout) {
    constexpr int BM = 128, BN = 64, BK = 32;
    constexpr int ASTR = BK + 4;
    constexpr int WSTR = BN + 4;
    __shared__ uint32_t As[BM * ASTR];
    __shared__ uint32_t Ws[BK * WSTR];

    const int tid = threadIdx.x;
    const int lane = tid & 31;
    const int wid = tid >> 5;
    const int g = lane >> 2;
    const int tig = lane & 3;
    const int warpM = (wid & 3) * 32;
    const int warpN = (wid >> 2) * 32;
    const int rowBase = blockIdx.x * BM;
    const int nBase = blockIdx.y * BN;

    float4 ra[4];
    float4 rw[2];

    auto loadA = [&](int kb) {
        #pragma unroll
        for (int i = 0; i < 4; i++) {
            int id = tid + i * 256;
            int row = id >> 3;
            int c4 = (id & 7) * 4;
            int grow = rowBase + row;
            if (grow < M)
                ra[i] = *reinterpret_cast<const float4*>(A + (size_t)grow * K + kb + c4);
            else
                ra[i] = make_float4(0.f, 0.f, 0.f, 0.f);
        }
    };
    auto loadW = [&](int kb) {
        #pragma unroll
        for (int i = 0; i < 2; i++) {
            int id = tid + i * 256;
            int row = id >> 4;
            int c4 = (id & 15) * 4;
            rw[i] = *reinterpret_cast<const float4*>(W + (size_t)(kb + row) * ldn + nBase + c4);
        }
    };
    auto storeA = [&]() {
        #pragma unroll
        for (int i = 0; i < 4; i++) {
            int id = tid + i * 256;
            int row = id >> 3;
            int c4 = (id & 7) * 4;
            uint32_t* p = &As[row * ASTR + c4];
            p[0] = f2tf32(ra[i].x);
            p[1] = f2tf32(ra[i].y);
            p[2] = f2tf32(ra[i].z);
            p[3] = f2tf32(ra[i].w);
        }
    };
    auto storeW = [&]() {
        #pragma unroll
        for (int i = 0; i < 2; i++) {
            int id = tid + i * 256;
            int row = id >> 4;
            int c4 = (id & 15) * 4;
            uint32_t* p = &Ws[row * WSTR + c4];
            p[0] = f2tf32(rw[i].x);
            p[1] = f2tf32(rw[i].y);
            p[2] = f2tf32(rw[i].z);
            p[3] = f2tf32(rw[i].w);
        }
    };

    float acc[2][4][4];
    #pragma unroll
    for (int m = 0; m < 2; m++)
        #pragma unroll
        for (int n = 0; n < 4; n++)
            #pragma unroll
            for (int q = 0; q < 4; q++) acc[m][n][q] = 0.f;

    loadA(0);
    loadW(0);

    for (int kb = 0; kb < K; kb += BK) {
        storeA();
        storeW();
        __syncthreads();
        if (kb + BK < K) { loadA(kb + BK); loadW(kb + BK); }

        #pragma unroll
        for (int ks = 0; ks < BK; ks += 8) {
            uint32_t af[2][4];
            #pragma unroll
            for (int m = 0; m < 2; m++) {
                int r0 = warpM + m * 16 + g;
                int r1 = r0 + 8;
                af[m][0] = As[r0 * ASTR + ks + tig];
                af[m][1] = As[r1 * ASTR + ks + tig];
                af[m][2] = As[r0 * ASTR + ks + tig + 4];
                af[m][3] = As[r1 * ASTR + ks + tig + 4];
            }
            uint32_t bf[4][2];
            #pragma unroll
            for (int n = 0; n < 4; n++) {
                int cn = warpN + n * 8 + g;
                bf[n][0] = Ws[(ks + tig) * WSTR + cn];
                bf[n][1] = Ws[(ks + tig + 4) * WSTR + cn];
            }
            #pragma unroll
            for (int m = 0; m < 2; m++)
                #pragma unroll
                for (int n = 0; n < 4; n++)
                    mma_tf32(acc[m][n], af[m][0], af[m][1], af[m][2], af[m][3],
                             bf[n][0], bf[n][1]);
        }
        __syncthreads();
    }

    #pragma unroll
    for (int n = 0; n < 4; n++) {
        int col = nBase + warpN + n * 8 + tig * 2;
        float bv0 = bias[col];
        float bv1 = bias[col + 1];
        #pragma unroll
        for (int m = 0; m < 2; m++) {
            #pragma unroll
            for (int hf = 0; hf < 2; hf++) {
                int row = rowBase + warpM + m * 16 + g + hf * 8;
                if (row >= M) continue;
                float sc = PSCALE ? pscale[row] : 1.f;
                float o0 = acc[m][n][hf * 2 + 0] + bv0;
                float o1 = acc[m][n][hf * 2 + 1] + bv1;
                if (RELU) { o0 = fmaxf(o0, 0.f); o1 = fmaxf(o1, 0.f); }
                o0 *= sc; o1 *= sc;
                if (OUTH) {
                    __half2 o = __floats2half2_rn(o0, o1);
                    *reinterpret_cast<__half2*>((__half*)Cout + (size_t)row * ldn + col) = o;
                } else {
                    *reinterpret_cast<float2*>((float*)Cout + (size_t)row * ldn + col) =
                        make_float2(o0, o1);
                }
            }
        }
    }
}

// ---------------------------------------------------------------------------
// f16 tensor-core GEMM (proven R4 kernel): A fp16, W fp32->fp16, fp32 accum.
// Block 128x64x32, 8 warps = 4(M) x 2(N). Used for MLP2.
// ---------------------------------------------------------------------------
template <bool RELU, bool OUTH>
__global__ __launch_bounds__(256) void gemm_f16_kernel(
        int M, int K, int ldn,
        const __half* __restrict__ A,
        const float* __restrict__ W,
        const float* __restrict__ bias,
        void* __restrict__ Cout) {
    constexpr int BM = 128, BK = 32;
    constexpr int ASTR = BK + 8;   // halves
    constexpr int WSTR = BK + 8;   // Wt is [BN][BK] transposed
    constexpr int BN = 64;
    __shared__ __half As[BM * ASTR];
    __shared__ __half Wt[BN * WSTR];

    const int tid = threadIdx.x;
    const int lane = tid & 31;
    const int wid = tid >> 5;
    const int g = lane >> 2;
    const int tig = lane & 3;
    const int warpM = (wid & 3) * 32;
    const int warpN = (wid >> 2) * 32;
    const int rowBase = blockIdx.x * BM;
    const int nBase = blockIdx.y * BN;

    uint2  ra[4];
    float4 rw[2];

    auto loadA = [&](int kb) {
        #pragma unroll
        for (int i = 0; i < 4; i++) {
            int id = tid + i * 256;        // 0..1023
            int row = id >> 3;             // 0..127
            int c4 = (id & 7) * 4;         // halves 0..28
            int grow = rowBase + row;
            if (grow < M)
                ra[i] = *reinterpret_cast<const uint2*>(A + (size_t)grow * K + kb + c4);
            else
                ra[i] = make_uint2(0u, 0u);
        }
    };
    auto loadW = [&](int kb) {
        #pragma unroll
        for (int i = 0; i < 2; i++) {
            int id = tid + i * 256;        // 0..511
            int k = id >> 4;               // 0..31
            int c4 = (id & 15) * 4;        // 0..60
            rw[i] = *reinterpret_cast<const float4*>(W + (size_t)(kb + k) * ldn + nBase + c4);
        }
    };
    auto storeA = [&]() {
        #pragma unroll
        for (int i = 0; i < 4; i++) {
            int id = tid + i * 256;
            int row = id >> 3;
            int c4 = (id & 7) * 4;
            *reinterpret_cast<uint2*>(&As[row * ASTR + c4]) = ra[i];
        }
    };
    auto storeW = [&]() {
        #pragma unroll
        for (int i = 0; i < 2; i++) {
            int id = tid + i * 256;
            int k = id >> 4;
            int c4 = (id & 15) * 4;
            Wt[(c4 + 0) * WSTR + k] = __float2half_rn(rw[i].x);
            Wt[(c4 + 1) * WSTR + k] = __float2half_rn(rw[i].y);
            Wt[(c4 + 2) * WSTR + k] = __float2half_rn(rw[i].z);
            Wt[(c4 + 3) * WSTR + k] = __float2half_rn(rw[i].w);
        }
    };

    float acc[2][4][4];
    #pragma unroll
    for (int m = 0; m < 2; m++)
        #pragma unroll
        for (int n = 0; n < 4; n++)
            #pragma unroll
            for (int q = 0; q < 4; q++) acc[m][n][q] = 0.f;

    loadA(0);
    loadW(0);

    for (int kb = 0; kb < K; kb += BK) {
        storeA();
        storeW();
        __syncthreads();
        if (kb + BK < K) { loadA(kb + BK); loadW(kb + BK); }

        #pragma unroll
        for (int ks = 0; ks < BK; ks += 16) {
            uint32_t af[2][4];
            #pragma unroll
            for (int m = 0; m < 2; m++) {
                int r0 = warpM + m * 16 + g;
                int r1 = r0 + 8;
                af[m][0] = *reinterpret_cast<const uint32_t*>(&As[r0 * ASTR + ks + tig * 2]);
                af[m][1] = *reinterpret_cast<const uint32_t*>(&As[r1 * ASTR + ks + tig * 2]);
                af[m][2] = *reinterpret_cast<const uint32_t*>(&As[r0 * ASTR + ks + tig * 2 + 8]);
                af[m][3] = *reinterpret_cast<const uint32_t*>(&As[r1 * ASTR + ks + tig * 2 + 8]);
            }
            uint32_t bf[4][2];
            #pragma unroll
            for (int n = 0; n < 4; n++) {
                int cn = warpN + n * 8 + g;
                bf[n][0] = *reinterpret_cast<const uint32_t*>(&Wt[cn * WSTR + ks + tig * 2]);
                bf[n][1] = *reinterpret_cast<const uint32_t*>(&Wt[cn * WSTR + ks + tig * 2 + 8]);
            }
            #pragma unroll
            for (int m = 0; m < 2; m++)
                #pragma unroll
                for (int n = 0; n < 4; n++)
                    mma_f16(acc[m][n], af[m][0], af[m][1], af[m][2], af[m][3],
                            bf[n][0], bf[n][1]);
        }
        __syncthreads();
    }

    #pragma unroll
    for (int n = 0; n < 4; n++) {
        int col = nBase + warpN + n * 8 + tig * 2;
        float bv0 = bias[col];
        float bv1 = bias[col + 1];
        #pragma unroll
        for (int m = 0; m < 2; m++) {
            #pragma unroll
            for (int hf = 0; hf < 2; hf++) {
                int row = rowBase + warpM + m * 16 + g + hf * 8;
                if (row >= M) continue;
                float o0 = acc[m][n][hf * 2 + 0] + bv0;
                float o1 = acc[m][n][hf * 2 + 1] + bv1;
                if (RELU) { o0 = fmaxf(o0, 0.f); o1 = fmaxf(o1, 0.f); }
                if (OUTH) {
                    __half2 o = __floats2half2_rn(o0, o1);
                    *reinterpret_cast<__half2*>((__half*)Cout + (size_t)row * ldn + col) = o;
                } else {
                    *reinterpret_cast<float2*>((float*)Cout + (size_t)row * ldn + col) =
                        make_float2(o0, o1);
                }
            }
        }
    }
}

// ---------------------------------------------------------------------------
extern "C" void kernel_launch(void* const* d_in, const int* in_sizes, int n_in,
                              void* d_out, int out_size) {
    const float* x   = (const float*)d_in[0];
    const int*   src = (const int*)d_in[1];
    const int*   dst = (const int*)d_in[2];
    const float* w1  = (const float*)d_in[3];
    const float* b1  = (const float*)d_in[4];
    const float* w2  = (const float*)d_in[5];
    const float* b2  = (const float*)d_in[6];
    const float* wm1 = (const float*)d_in[7];
    const float* bm1 = (const float*)d_in[8];
    const float* wm2 = (const float*)d_in[9];
    const float* bm2 = (const float*)d_in[10];

    const int n = in_sizes[0] / 128;
    const int e = in_sizes[1];

    int *deg_in, *deg_out, *row_ptr, *cursor, *sorted_src, *partial;
    float *onorm, *inorm, *agg, *h;
    __half *xh, *h1h, *h3h;
    cudaGetSymbolAddress((void**)&deg_in, g_deg_in);
    cudaGetSymbolAddress((void**)&deg_out, g_deg_out);
    cudaGetSymbolAddress((void**)&row_ptr, g_row_ptr);
    cudaGetSymbolAddress((void**)&cursor, g_cursor);
    cudaGetSymbolAddress((void**)&partial, g_partial);
    cudaGetSymbolAddress((void**)&sorted_src, g_sorted_src);
    cudaGetSymbolAddress((void**)&onorm, g_out_norm);
    cudaGetSymbolAddress((void**)&inorm, g_in_norm);
    cudaGetSymbolAddress((void**)&xh, g_xh);
    cudaGetSymbolAddress((void**)&h1h, g_h1h);
    cudaGetSymbolAddress((void**)&agg, g_agg);
    cudaGetSymbolAddress((void**)&h, g_h);
    cudaGetSymbolAddress((void**)&h3h, g_h3h);

    const int nb = (n + 255) / 256;
    const int eb = (e + 511) / 512;
    const int nChunks = (n + SCAN_CHUNK - 1) / SCAN_CHUNK;

    // --- CSR build (parallel 3-phase scan, finalize fused into phase 3) ---
    zero_deg_kernel<<<nb, 256>>>(n, deg_in, deg_out);
    hist_kernel<<<eb, 512>>>(e, src, dst, deg_in, deg_out);
    scan_p1_kernel<<<nChunks, 1024>>>(n, deg_in, partial);
    scan_p2_kernel<<<1, 1024>>>(nChunks, n, partial, row_ptr);
    scan_p3_kernel<<<nChunks, 1024>>>(n, deg_in, deg_out, partial,
                                      row_ptr, cursor, onorm, inorm);
    scatter_kernel<<<eb, 512>>>(e, src, dst, cursor, sorted_src);

    // --- x -> fp16 prescaled by out_norm ---
    convert_x_kernel<<<(n * 32 + 255) / 256, 256>>>(n, x, onorm, xh);

    const int aggBlocks = (n + 7) / 8;
    const dim3 g2((n + 127) / 128, 2);
    const dim3 g4((n + 127) / 128, 4);
    const dim3 g1((n + 127) / 128, 1);

    // --- conv1 ---
    agg_hpair_kernel<<<aggBlocks, 256>>>(n, xh, row_ptr, sorted_src, inorm, agg);
    gemm_tf32_kernel<true, true, true><<<g2, 256>>>(n, 128, 128, agg, w1, b1, onorm, h1h);

    // --- conv2 ---
    agg_hpair_kernel<<<aggBlocks, 256>>>(n, h1h, row_ptr, sorted_src, inorm, agg);
    gemm_tf32_kernel<true, false, false><<<g2, 256>>>(n, 128, 128, agg, w2, b2, nullptr, h);

    // --- MLP: hidden stored fp16 (mantissa-equivalent to tf32 rounding) ---
    gemm_tf32_kernel<true, false, true><<<g4, 256>>>(n, 128, 256, h, wm1, bm1, nullptr, h3h);
    gemm_f16_kernel<false, false><<<g1, 256>>>(n, 256, 64, h3h, wm2, bm2, d_out);
}

// round 17
// speedup vs baseline: 1.0766x; 1.0353x over previous
#include <cuda_runtime.h>
#include <cuda_fp16.h>
#include <cstdint>

// ---------------------------------------------------------------------------
// GCN: fp16 feature gather with pairwise HADD2 (proven agg, now fp16 out),
// fp32 accum, f16-mma GEMMs (proven R4 kernel + PSCALE) for all layers.
// All intermediates fp16 (mantissa-equivalent to tf32 rounding).
// CSR build with 3-phase parallel scan (fused finalize).
// ---------------------------------------------------------------------------

#define N_MAX 100000
#define E_MAX 3200000
#define SCAN_CHUNK 4096
#define MAX_CHUNKS ((N_MAX + SCAN_CHUNK - 1) / SCAN_CHUNK + 1)

__device__ int    g_deg_in[N_MAX];
__device__ int    g_deg_out[N_MAX];
__device__ int    g_row_ptr[N_MAX + 1];
__device__ int    g_cursor[N_MAX];
__device__ int    g_partial[MAX_CHUNKS];
__device__ int    g_sorted_src[E_MAX];
__device__ float  g_out_norm[N_MAX];
__device__ float  g_in_norm[N_MAX];
__device__ __half g_xh[(size_t)N_MAX * 128];    // conv1 gather features
__device__ __half g_aggh[(size_t)N_MAX * 128];  // agg output (GEMM A)
__device__ __half g_h1h[(size_t)N_MAX * 128];   // conv1 out (conv2 gather feats)
__device__ __half g_hh[(size_t)N_MAX * 128];    // h2
__device__ __half g_h3h[(size_t)N_MAX * 256];   // MLP hidden

// ---------------------------------------------------------------------------
__global__ void zero_deg_kernel(int n, int* deg_in, int* deg_out) {
    int i = blockIdx.x * blockDim.x + threadIdx.x;
    if (i < n) { deg_in[i] = 0; deg_out[i] = 0; }
}

__global__ void hist_kernel(int e, const int* __restrict__ src,
                            const int* __restrict__ dst,
                            int* deg_in, int* deg_out) {
    int i = blockIdx.x * blockDim.x + threadIdx.x;
    if (i < e) {
        atomicAdd(&deg_out[src[i]], 1);
        atomicAdd(&deg_in[dst[i]], 1);
    }
}

// --- 3-phase parallel scan over deg_in ---
__global__ void scan_p1_kernel(int n, const int* __restrict__ deg, int* __restrict__ partial) {
    __shared__ int wsum[32];
    int i0 = blockIdx.x * SCAN_CHUNK + threadIdx.x * 4;
    int t = 0;
    if (i0 + 3 < n) {
        int4 v = *reinterpret_cast<const int4*>(deg + i0);
        t = v.x + v.y + v.z + v.w;
    } else {
        #pragma unroll
        for (int k = 0; k < 4; k++) if (i0 + k < n) t += deg[i0 + k];
    }
    #pragma unroll
    for (int o = 16; o > 0; o >>= 1) t += __shfl_down_sync(0xffffffffu, t, o);
    if ((threadIdx.x & 31) == 0) wsum[threadIdx.x >> 5] = t;
    __syncthreads();
    if (threadIdx.x < 32) {
        int v = wsum[threadIdx.x];
        #pragma unroll
        for (int o = 16; o > 0; o >>= 1) v += __shfl_down_sync(0xffffffffu, v, o);
        if (threadIdx.x == 0) partial[blockIdx.x] = v;
    }
}

__global__ void scan_p2_kernel(int nb, int n, int* __restrict__ partial,
                               int* __restrict__ row_ptr) {
    __shared__ int wsum[32];
    int tid = threadIdx.x;
    int lane = tid & 31;
    int wid = tid >> 5;
    int v = (tid < nb) ? partial[tid] : 0;
    int x = v;
    #pragma unroll
    for (int o = 1; o < 32; o <<= 1) {
        int u = __shfl_up_sync(0xffffffffu, x, o);
        if (lane >= o) x += u;
    }
    if (lane == 31) wsum[wid] = x;
    __syncthreads();
    if (wid == 0) {
        int y = wsum[lane];
        #pragma unroll
        for (int o = 1; o < 32; o <<= 1) {
            int u = __shfl_up_sync(0xffffffffu, y, o);
            if (lane >= o) y += u;
        }
        wsum[lane] = y;
    }
    __syncthreads();
    int excl = x - v + (wid > 0 ? wsum[wid - 1] : 0);
    if (tid < nb) partial[tid] = excl;
    if (tid == nb - 1) row_ptr[n] = excl + v;
}

__global__ void scan_p3_kernel(int n, const int* __restrict__ deg_in,
                               const int* __restrict__ deg_out,
                               const int* __restrict__ partial,
                               int* __restrict__ row_ptr, int* __restrict__ cursor,
                               float* __restrict__ onorm, float* __restrict__ inorm) {
    __shared__ int wsum[32];
    int i0 = blockIdx.x * SCAN_CHUNK + threadIdx.x * 4;
    int v0 = 0, v1 = 0, v2 = 0, v3 = 0;
    int d0 = 1, d1 = 1, d2 = 1, d3 = 1;
    if (i0 + 3 < n) {
        int4 v = *reinterpret_cast<const int4*>(deg_in + i0);
        v0 = v.x; v1 = v.y; v2 = v.z; v3 = v.w;
        int4 d = *reinterpret_cast<const int4*>(deg_out + i0);
        d0 = d.x; d1 = d.y; d2 = d.z; d3 = d.w;
    } else {
        if (i0 + 0 < n) { v0 = deg_in[i0 + 0]; d0 = deg_out[i0 + 0]; }
        if (i0 + 1 < n) { v1 = deg_in[i0 + 1]; d1 = deg_out[i0 + 1]; }
        if (i0 + 2 < n) { v2 = deg_in[i0 + 2]; d2 = deg_out[i0 + 2]; }
        if (i0 + 3 < n) { v3 = deg_in[i0 + 3]; d3 = deg_out[i0 + 3]; }
    }
    int t = v0 + v1 + v2 + v3;
    int lane = threadIdx.x & 31;
    int wid = threadIdx.x >> 5;
    int x = t;
    #pragma unroll
    for (int o = 1; o < 32; o <<= 1) {
        int u = __shfl_up_sync(0xffffffffu, x, o);
        if (lane >= o) x += u;
    }
    if (lane == 31) wsum[wid] = x;
    __syncthreads();
    if (wid == 0) {
        int y = wsum[lane];
        #pragma unroll
        for (int o = 1; o < 32; o <<= 1) {
            int u = __shfl_up_sync(0xffffffffu, y, o);
            if (lane >= o) y += u;
        }
        wsum[lane] = y;
    }
    __syncthreads();
    int excl = partial[blockIdx.x] + (wid > 0 ? wsum[wid - 1] : 0) + (x - t);
    int e0 = excl, e1 = e0 + v0, e2 = e1 + v1, e3 = e2 + v2;
    if (i0 + 0 < n) {
        row_ptr[i0 + 0] = e0; cursor[i0 + 0] = e0;
        inorm[i0 + 0] = rsqrtf((float)max(v0, 1));
        onorm[i0 + 0] = rsqrtf((float)max(d0, 1));
    }
    if (i0 + 1 < n) {
        row_ptr[i0 + 1] = e1; cursor[i0 + 1] = e1;
        inorm[i0 + 1] = rsqrtf((float)max(v1, 1));
        onorm[i0 + 1] = rsqrtf((float)max(d1, 1));
    }
    if (i0 + 2 < n) {
        row_ptr[i0 + 2] = e2; cursor[i0 + 2] = e2;
        inorm[i0 + 2] = rsqrtf((float)max(v2, 1));
        onorm[i0 + 2] = rsqrtf((float)max(d2, 1));
    }
    if (i0 + 3 < n) {
        row_ptr[i0 + 3] = e3; cursor[i0 + 3] = e3;
        inorm[i0 + 3] = rsqrtf((float)max(v3, 1));
        onorm[i0 + 3] = rsqrtf((float)max(d3, 1));
    }
}

__global__ void scatter_kernel(int e, const int* __restrict__ src,
                               const int* __restrict__ dst,
                               int* cursor, int* __restrict__ sorted_src) {
    int i = blockIdx.x * blockDim.x + threadIdx.x;
    if (i < e) {
        int d = dst[i];
        int pos = atomicAdd(&cursor[d], 1);
        sorted_src[pos] = src[i];
    }
}

// xh[i, :] = fp16(x[i, :] * out_norm[i]); one thread per 4 features.
__global__ void convert_x_kernel(int n, const float* __restrict__ x,
                                 const float* __restrict__ onorm,
                                 __half* __restrict__ xh) {
    int idx = blockIdx.x * blockDim.x + threadIdx.x;
    if (idx >= n * 32) return;
    int row = idx >> 5;
    float s = onorm[row];
    float4 v = *reinterpret_cast<const float4*>(x + (size_t)idx * 4);
    __half2 o0 = __floats2half2_rn(v.x * s, v.y * s);
    __half2 o1 = __floats2half2_rn(v.z * s, v.w * s);
    uint2 ov;
    ov.x = *reinterpret_cast<uint32_t*>(&o0);
    ov.y = *reinterpret_cast<uint32_t*>(&o1);
    *reinterpret_cast<uint2*>(xh + (size_t)idx * 4) = ov;
}

// ---------------------------------------------------------------------------
__device__ __forceinline__ __half2 u2h(uint32_t u) {
    __half2 h;
    *reinterpret_cast<uint32_t*>(&h) = u;
    return h;
}

// fp16 gather aggregation with pairwise HADD2 (proven inner loop), fp16 out.
__global__ void agg_hpair_kernel(int n, const __half* __restrict__ feat,
                                 const int* __restrict__ row_ptr,
                                 const int* __restrict__ srcs,
                                 const float* __restrict__ inorm,
                                 __half* __restrict__ out) {
    int warp = (blockIdx.x * blockDim.x + threadIdx.x) >> 5;
    if (warp >= n) return;
    const int lane = threadIdx.x & 31;
    const int beg = row_ptr[warp];
    const int end = row_ptr[warp + 1];
    const __half* fl = feat + lane * 4;

    float a0 = 0.f, a1 = 0.f, a2 = 0.f, a3 = 0.f;
    float b0 = 0.f, b1 = 0.f, b2 = 0.f, b3 = 0.f;

    int i = beg;
    for (; i + 32 <= end; i += 32) {
        int s = __ldg(srcs + i + lane);
        #pragma unroll
        for (int j = 0; j < 32; j += 4) {
            int s0 = __shfl_sync(0xffffffffu, s, j + 0);
            int s1 = __shfl_sync(0xffffffffu, s, j + 1);
            int s2 = __shfl_sync(0xffffffffu, s, j + 2);
            int s3 = __shfl_sync(0xffffffffu, s, j + 3);
            uint2 w0 = *reinterpret_cast<const uint2*>(fl + (size_t)s0 * 128);
            uint2 w1 = *reinterpret_cast<const uint2*>(fl + (size_t)s1 * 128);
            uint2 w2 = *reinterpret_cast<const uint2*>(fl + (size_t)s2 * 128);
            uint2 w3 = *reinterpret_cast<const uint2*>(fl + (size_t)s3 * 128);
            __half2 p0 = __hadd2(u2h(w0.x), u2h(w1.x));
            __half2 p1 = __hadd2(u2h(w0.y), u2h(w1.y));
            __half2 q0 = __hadd2(u2h(w2.x), u2h(w3.x));
            __half2 q1 = __hadd2(u2h(w2.y), u2h(w3.y));
            float2 f;
            f = __half22float2(p0); a0 += f.x; a1 += f.y;
            f = __half22float2(p1); a2 += f.x; a3 += f.y;
            f = __half22float2(q0); b0 += f.x; b1 += f.y;
            f = __half22float2(q1); b2 += f.x; b3 += f.y;
        }
    }
    if (i < end) {
        int cnt = end - i;
        int s = 0;
        if (lane < cnt) s = __ldg(srcs + i + lane);
        int j = 0;
        for (; j + 2 <= cnt; j += 2) {
            int s0 = __shfl_sync(0xffffffffu, s, j + 0);
            int s1 = __shfl_sync(0xffffffffu, s, j + 1);
            uint2 w0 = *reinterpret_cast<const uint2*>(fl + (size_t)s0 * 128);
            uint2 w1 = *reinterpret_cast<const uint2*>(fl + (size_t)s1 * 128);
            __half2 p0 = __hadd2(u2h(w0.x), u2h(w1.x));
            __half2 p1 = __hadd2(u2h(w0.y), u2h(w1.y));
            float2 f;
            f = __half22float2(p0); a0 += f.x; a1 += f.y;
            f = __half22float2(p1); a2 += f.x; a3 += f.y;
        }
        if (j < cnt) {
            int s0 = __shfl_sync(0xffffffffu, s, j);
            uint2 w0 = *reinterpret_cast<const uint2*>(fl + (size_t)s0 * 128);
            float2 f;
            f = __half22float2(u2h(w0.x)); a0 += f.x; a1 += f.y;
            f = __half22float2(u2h(w0.y)); a2 += f.x; a3 += f.y;
        }
    }
    float iw = inorm[warp];
    __half2 o0 = __floats2half2_rn((a0 + b0) * iw, (a1 + b1) * iw);
    __half2 o1 = __floats2half2_rn((a2 + b2) * iw, (a3 + b3) * iw);
    uint2 ov;
    ov.x = *reinterpret_cast<uint32_t*>(&o0);
    ov.y = *reinterpret_cast<uint32_t*>(&o1);
    *reinterpret_cast<uint2*>(out + (size_t)warp * 128 + lane * 4) = ov;
}

// ---------------------------------------------------------------------------
__device__ __forceinline__ void mma_f16(float c[4], uint32_t a0, uint32_t a1,
                                        uint32_t a2, uint32_t a3,
                                        uint32_t b0, uint32_t b1) {
    asm volatile(
        "mma.sync.aligned.m16n8k16.row.col.f32.f16.f16.f32 "
        "{%0,%1,%2,%3}, {%4,%5,%6,%7}, {%8,%9}, {%0,%1,%2,%3};\n"
        : "+f"(c[0]), "+f"(c[1]), "+f"(c[2]), "+f"(c[3])
        : "r"(a0), "r"(a1), "r"(a2), "r"(a3), "r"(b0), "r"(b1));
}

// ---------------------------------------------------------------------------
// f16 tensor-core GEMM (proven R4 kernel + PSCALE): A fp16, W fp32->fp16,
// fp32 accum. Block 128x64x32, 8 warps = 4(M) x 2(N).
// ---------------------------------------------------------------------------
template <bool RELU, bool PSCALE, bool OUTH>
__global__ __launch_bounds__(256) void gemm_f16_kernel(
        int M, int K, int ldn,
        const __half* __restrict__ A,
        const float* __restrict__ W,
        const float* __restrict__ bias,
        const float* __restrict__ pscale,
        void* __restrict__ Cout) {
    constexpr int BM = 128, BN = 64, BK = 32;
    constexpr int ASTR = BK + 8;   // halves
    constexpr int WSTR = BK + 8;   // Wt is [BN][BK] transposed
    __shared__ __half As[BM * ASTR];
    __shared__ __half Wt[BN * WSTR];

    const int tid = threadIdx.x;
    const int lane = tid & 31;
    const int wid = tid >> 5;
    const int g = lane >> 2;
    const int tig = lane & 3;
    const int warpM = (wid & 3) * 32;
    const int warpN = (wid >> 2) * 32;
    const int rowBase = blockIdx.x * BM;
    const int nBase = blockIdx.y * BN;

    uint2  ra[4];
    float4 rw[2];

    auto loadA = [&](int kb) {
        #pragma unroll
        for (int i = 0; i < 4; i++) {
            int id = tid + i * 256;        // 0..1023
            int row = id >> 3;             // 0..127
            int c4 = (id & 7) * 4;         // halves 0..28
            int grow = rowBase + row;
            if (grow < M)
                ra[i] = *reinterpret_cast<const uint2*>(A + (size_t)grow * K + kb + c4);
            else
                ra[i] = make_uint2(0u, 0u);
        }
    };
    auto loadW = [&](int kb) {
        #pragma unroll
        for (int i = 0; i < 2; i++) {
            int id = tid + i * 256;        // 0..511
            int k = id >> 4;               // 0..31
            int c4 = (id & 15) * 4;        // 0..60
            rw[i] = *reinterpret_cast<const float4*>(W + (size_t)(kb + k) * ldn + nBase + c4);
        }
    };
    auto storeA = [&]() {
        #pragma unroll
        for (int i = 0; i < 4; i++) {
            int id = tid + i * 256;
            int row = id >> 3;
            int c4 = (id & 7) * 4;
            *reinterpret_cast<uint2*>(&As[row * ASTR + c4]) = ra[i];
        }
    };
    auto storeW = [&]() {
        #pragma unroll
        for (int i = 0; i < 2; i++) {
            int id = tid + i * 256;
            int k = id >> 4;
            int c4 = (id & 15) * 4;
            Wt[(c4 + 0) * WSTR + k] = __float2half_rn(rw[i].x);
            Wt[(c4 + 1) * WSTR + k] = __float2half_rn(rw[i].y);
            Wt[(c4 + 2) * WSTR + k] = __float2half_rn(rw[i].z);
            Wt[(c4 + 3) * WSTR + k] = __float2half_rn(rw[i].w);
        }
    };

    float acc[2][4][4];
    #pragma unroll
    for (int m = 0; m < 2; m++)
        #pragma unroll
        for (int n = 0; n < 4; n++)
            #pragma unroll
            for (int q = 0; q < 4; q++) acc[m][n][q] = 0.f;

    loadA(0);
    loadW(0);

    for (int kb = 0; kb < K; kb += BK) {
        storeA();
        storeW();
        __syncthreads();
        if (kb + BK < K) { loadA(kb + BK); loadW(kb + BK); }

        #pragma unroll
        for (int ks = 0; ks < BK; ks += 16) {
            uint32_t af[2][4];
            #pragma unroll
            for (int m = 0; m < 2; m++) {
                int r0 = warpM + m * 16 + g;
                int r1 = r0 + 8;
                af[m][0] = *reinterpret_cast<const uint32_t*>(&As[r0 * ASTR + ks + tig * 2]);
                af[m][1] = *reinterpret_cast<const uint32_t*>(&As[r1 * ASTR + ks + tig * 2]);
                af[m][2] = *reinterpret_cast<const uint32_t*>(&As[r0 * ASTR + ks + tig * 2 + 8]);
                af[m][3] = *reinterpret_cast<const uint32_t*>(&As[r1 * ASTR + ks + tig * 2 + 8]);
            }
            uint32_t bf[4][2];
            #pragma unroll
            for (int n = 0; n < 4; n++) {
                int cn = warpN + n * 8 + g;
                bf[n][0] = *reinterpret_cast<const uint32_t*>(&Wt[cn * WSTR + ks + tig * 2]);
                bf[n][1] = *reinterpret_cast<const uint32_t*>(&Wt[cn * WSTR + ks + tig * 2 + 8]);
            }
            #pragma unroll
            for (int m = 0; m < 2; m++)
                #pragma unroll
                for (int n = 0; n < 4; n++)
                    mma_f16(acc[m][n], af[m][0], af[m][1], af[m][2], af[m][3],
                            bf[n][0], bf[n][1]);
        }
        __syncthreads();
    }

    #pragma unroll
    for (int n = 0; n < 4; n++) {
        int col = nBase + warpN + n * 8 + tig * 2;
        float bv0 = bias[col];
        float bv1 = bias[col + 1];
        #pragma unroll
        for (int m = 0; m < 2; m++) {
            #pragma unroll
            for (int hf = 0; hf < 2; hf++) {
                int row = rowBase + warpM + m * 16 + g + hf * 8;
                if (row >= M) continue;
                float sc = PSCALE ? pscale[row] : 1.f;
                float o0 = acc[m][n][hf * 2 + 0] + bv0;
                float o1 = acc[m][n][hf * 2 + 1] + bv1;
                if (RELU) { o0 = fmaxf(o0, 0.f); o1 = fmaxf(o1, 0.f); }
                o0 *= sc; o1 *= sc;
                if (OUTH) {
                    __half2 o = __floats2half2_rn(o0, o1);
                    *reinterpret_cast<__half2*>((__half*)Cout + (size_t)row * ldn + col) = o;
                } else {
                    *reinterpret_cast<float2*>((float*)Cout + (size_t)row * ldn + col) =
                        make_float2(o0, o1);
                }
            }
        }
    }
}

// ---------------------------------------------------------------------------
extern "C" void kernel_launch(void* const* d_in, const int* in_sizes, int n_in,
                              void* d_out, int out_size) {
    const float* x   = (const float*)d_in[0];
    const int*   src = (const int*)d_in[1];
    const int*   dst = (const int*)d_in[2];
    const float* w1  = (const float*)d_in[3];
    const float* b1  = (const float*)d_in[4];
    const float* w2  = (const float*)d_in[5];
    const float* b2  = (const float*)d_in[6];
    const float* wm1 = (const float*)d_in[7];
    const float* bm1 = (const float*)d_in[8];
    const float* wm2 = (const float*)d_in[9];
    const float* bm2 = (const float*)d_in[10];

    const int n = in_sizes[0] / 128;
    const int e = in_sizes[1];

    int *deg_in, *deg_out, *row_ptr, *cursor, *sorted_src, *partial;
    float *onorm, *inorm;
    __half *xh, *aggh, *h1h, *hh, *h3h;
    cudaGetSymbolAddress((void**)&deg_in, g_deg_in);
    cudaGetSymbolAddress((void**)&deg_out, g_deg_out);
    cudaGetSymbolAddress((void**)&row_ptr, g_row_ptr);
    cudaGetSymbolAddress((void**)&cursor, g_cursor);
    cudaGetSymbolAddress((void**)&partial, g_partial);
    cudaGetSymbolAddress((void**)&sorted_src, g_sorted_src);
    cudaGetSymbolAddress((void**)&onorm, g_out_norm);
    cudaGetSymbolAddress((void**)&inorm, g_in_norm);
    cudaGetSymbolAddress((void**)&xh, g_xh);
    cudaGetSymbolAddress((void**)&aggh, g_aggh);
    cudaGetSymbolAddress((void**)&h1h, g_h1h);
    cudaGetSymbolAddress((void**)&hh, g_hh);
    cudaGetSymbolAddress((void**)&h3h, g_h3h);

    const int nb = (n + 255) / 256;
    const int eb = (e + 511) / 512;
    const int nChunks = (n + SCAN_CHUNK - 1) / SCAN_CHUNK;

    // --- CSR build (parallel 3-phase scan, finalize fused into phase 3) ---
    zero_deg_kernel<<<nb, 256>>>(n, deg_in, deg_out);
    hist_kernel<<<eb, 512>>>(e, src, dst, deg_in, deg_out);
    scan_p1_kernel<<<nChunks, 1024>>>(n, deg_in, partial);
    scan_p2_kernel<<<1, 1024>>>(nChunks, n, partial, row_ptr);
    scan_p3_kernel<<<nChunks, 1024>>>(n, deg_in, deg_out, partial,
                                      row_ptr, cursor, onorm, inorm);
    scatter_kernel<<<eb, 512>>>(e, src, dst, cursor, sorted_src);

    // --- x -> fp16 prescaled by out_norm ---
    convert_x_kernel<<<(n * 32 + 255) / 256, 256>>>(n, x, onorm, xh);

    const int aggBlocks = (n + 7) / 8;
    const dim3 g2((n + 127) / 128, 2);
    const dim3 g4((n + 127) / 128, 4);
    const dim3 g1((n + 127) / 128, 1);

    // --- conv1: agg(xh) -> fp16; f16 GEMM; out fp16 * out_norm ---
    agg_hpair_kernel<<<aggBlocks, 256>>>(n, xh, row_ptr, sorted_src, inorm, aggh);
    gemm_f16_kernel<true, true, true><<<g2, 256>>>(n, 128, 128, aggh, w1, b1, onorm, h1h);

    // --- conv2: agg(h1h) -> fp16; f16 GEMM; out fp16 ---
    agg_hpair_kernel<<<aggBlocks, 256>>>(n, h1h, row_ptr, sorted_src, inorm, aggh);
    gemm_f16_kernel<true, false, true><<<g2, 256>>>(n, 128, 128, aggh, w2, b2, nullptr, hh);

    // --- MLP: hidden fp16; final out fp32 ---
    gemm_f16_kernel<true, false, true><<<g4, 256>>>(n, 128, 256, hh, wm1, bm1, nullptr, h3h);
    gemm_f16_kernel<false, false, false><<<g1, 256>>>(n, 256, 64, h3h, wm2, bm2, nullptr, d_out);
}